// round 2
// baseline (speedup 1.0000x reference)
#include <cuda_runtime.h>
#include <cuda_bf16.h>

#define NN 50000
#define EE 800000
#define FF 64
#define HH 4

// ---------------- scratch (device globals; no allocation allowed) ----------------
__device__ __align__(16) float g_xln[NN * FF];       // LayerNorm output = Tx0
__device__ __align__(16) float g_deg[NN];            // deg, then dinv in-place
__device__ __align__(16) float g_w[EE];              // scaled-Laplacian edge weights
__device__ __align__(16) float g_tx1[NN * FF];
__device__ __align__(16) float g_tx2[NN * FF];       // raw prop(Tx1); 2*.-Tx0 applied in GEMM
__device__ __align__(16) float g_h[NN * FF];         // Cheb output (leaky)
__device__ __align__(16) float g_xh[NN * HH * FF];   // GAT projected features
__device__ __align__(16) float g_asrc[NN * HH];
__device__ __align__(16) float g_adst[NN * HH];
__device__ __align__(16) float g_denom[NN * HH];     // softmax denominators (incl. self loop + eps)
__device__ __align__(16) float g_ex[EE * HH];        // exp(e) per edge per head

// ---------------- helpers ----------------
__device__ __forceinline__ void red4(float* p, float4 v) {
    asm volatile("red.global.add.v4.f32 [%0], {%1, %2, %3, %4};"
                 :: "l"(p), "f"(v.x), "f"(v.y), "f"(v.z), "f"(v.w) : "memory");
}
__device__ __forceinline__ float lrelu(float x, float s) { return x >= 0.f ? x : s * x; }
#define FULLM 0xffffffffu

// ---------------- zeroing (scratch + out in one pass) ----------------
__global__ void k_zero_scratch(float* __restrict__ out, int outn) {
    int i = blockIdx.x * blockDim.x + threadIdx.x;
    if (i < NN * FF) { g_tx1[i] = 0.f; g_tx2[i] = 0.f; }
    if (i < outn) out[i] = 0.f;
    if (i < NN) g_deg[i] = 0.f;
}

// ---------------- LayerNorm: warp per row ----------------
__global__ void k_ln(const float* __restrict__ x, const float* __restrict__ gamma,
                     const float* __restrict__ beta, int n) {
    int warp = threadIdx.x >> 5, lane = threadIdx.x & 31;
    int r = blockIdx.x * 8 + warp;
    if (r >= n) return;
    float2 v = *(const float2*)(x + r * FF + lane * 2);
    float s = v.x + v.y;
    #pragma unroll
    for (int o = 16; o; o >>= 1) s += __shfl_xor_sync(FULLM, s, o);
    float mu = s * (1.f / FF);
    float dx = v.x - mu, dy = v.y - mu;
    float sq = dx * dx + dy * dy;
    #pragma unroll
    for (int o = 16; o; o >>= 1) sq += __shfl_xor_sync(FULLM, sq, o);
    float inv = rsqrtf(sq * (1.f / FF) + 1e-5f);
    float2 gm = *(const float2*)(gamma + lane * 2);
    float2 bt = *(const float2*)(beta + lane * 2);
    float2 o2;
    o2.x = dx * inv * gm.x + bt.x;
    o2.y = dy * inv * gm.y + bt.y;
    *(float2*)(g_xln + r * FF + lane * 2) = o2;
}

// ---------------- degree / dinv / edge weights ----------------
__global__ void k_deg(const int* __restrict__ ei, const float* __restrict__ ea, int E) {
    int e = blockIdx.x * blockDim.x + threadIdx.x;
    if (e >= E) return;
    atomicAdd(&g_deg[ei[e]], ea[e]);
}
__global__ void k_dinv(int n) {
    int i = blockIdx.x * blockDim.x + threadIdx.x;
    if (i >= n) return;
    float d = g_deg[i];
    g_deg[i] = d > 0.f ? rsqrtf(d) : 0.f;
}
__global__ void k_w(const int* __restrict__ ei, const float* __restrict__ ea, int E) {
    int e = blockIdx.x * blockDim.x + threadIdx.x;
    if (e >= E) return;
    g_w[e] = -(g_deg[ei[e]] * ea[e] * g_deg[ei[E + e]]);
}

// ---------------- propagation: 16 threads per edge, float4 vector reds ----------------
__device__ __forceinline__ void prop_body(const int* __restrict__ ei, int E,
                                          const float* __restrict__ srcf, float* __restrict__ dstf) {
    int tid = blockIdx.x * blockDim.x + threadIdx.x;
    int e = tid >> 4;
    if (e >= E) return;
    int c = (tid & 15) << 2;
    int s = __ldg(&ei[e]);
    int d = __ldg(&ei[E + e]);
    float wv = __ldg(&g_w[e]);
    float4 v = *(const float4*)(srcf + s * FF + c);
    red4(dstf + d * FF + c, make_float4(v.x * wv, v.y * wv, v.z * wv, v.w * wv));
}
__global__ void k_prop1(const int* __restrict__ ei, int E) { prop_body(ei, E, g_xln, g_tx1); }
__global__ void k_prop2(const int* __restrict__ ei, int E) { prop_body(ei, E, g_tx1, g_tx2); }

// ---------------- fused Cheb GEMM: [Tx0|Tx1|2*Tx2-Tx0] @ [192,64] + bias, leaky ----------------
__global__ void k_cheb(const float* __restrict__ W, const float* __restrict__ bias, int n) {
    __shared__ float sW[192 * 64];   // exactly 48KB; cheb_w [3,64,64] is already this layout
    for (int i = threadIdx.x; i < 192 * 64; i += 256) sW[i] = W[i];
    __syncthreads();
    int warp = threadIdx.x >> 5, lane = threadIdx.x & 31;
    int r0 = (blockIdx.x * 8 + warp) * 2;
    int r1 = r0 + 1;
    if (r0 >= n) return;
    bool v1 = r1 < n;
    float a0r0 = g_xln[r0 * FF + lane], a1r0 = g_xln[r0 * FF + lane + 32];
    float b0r0 = g_tx1[r0 * FF + lane], b1r0 = g_tx1[r0 * FF + lane + 32];
    float c0r0 = 2.f * g_tx2[r0 * FF + lane] - a0r0;
    float c1r0 = 2.f * g_tx2[r0 * FF + lane + 32] - a1r0;
    float a0r1 = v1 ? g_xln[r1 * FF + lane] : 0.f, a1r1 = v1 ? g_xln[r1 * FF + lane + 32] : 0.f;
    float b0r1 = v1 ? g_tx1[r1 * FF + lane] : 0.f, b1r1 = v1 ? g_tx1[r1 * FF + lane + 32] : 0.f;
    float c0r1 = v1 ? 2.f * g_tx2[r1 * FF + lane] - a0r1 : 0.f;
    float c1r1 = v1 ? 2.f * g_tx2[r1 * FF + lane + 32] - a1r1 : 0.f;

    float acc00 = 0.f, acc01 = 0.f, acc10 = 0.f, acc11 = 0.f;
#define CHB(RA, RB, BASE)                                           \
    _Pragma("unroll")                                               \
    for (int kk = 0; kk < 32; kk++) {                               \
        float wa = sW[(BASE + kk) * 64 + lane];                     \
        float wb = sW[(BASE + kk) * 64 + lane + 32];                \
        float va = __shfl_sync(FULLM, RA, kk);                      \
        float vb = __shfl_sync(FULLM, RB, kk);                      \
        acc00 = fmaf(va, wa, acc00); acc01 = fmaf(va, wb, acc01);   \
        acc10 = fmaf(vb, wa, acc10); acc11 = fmaf(vb, wb, acc11);   \
    }
    CHB(a0r0, a0r1, 0)   CHB(a1r0, a1r1, 32)
    CHB(b0r0, b0r1, 64)  CHB(b1r0, b1r1, 96)
    CHB(c0r0, c0r1, 128) CHB(c1r0, c1r1, 160)
#undef CHB
    float bl = __ldg(&bias[lane]), bh = __ldg(&bias[lane + 32]);
    g_h[r0 * FF + lane]      = lrelu(acc00 + bl, 0.01f);
    g_h[r0 * FF + lane + 32] = lrelu(acc01 + bh, 0.01f);
    if (v1) {
        g_h[r1 * FF + lane]      = lrelu(acc10 + bl, 0.01f);
        g_h[r1 * FF + lane + 32] = lrelu(acc11 + bh, 0.01f);
    }
}

// ---------------- GAT projection: h @ gat_w[64,256]; 2 column-chunks of 128 ----------------
__global__ void k_gatgemm(const float* __restrict__ W, int n) {
    __shared__ float sW[64 * 128];   // 32KB chunk
    int chunk = blockIdx.y;
    for (int i = threadIdx.x; i < 64 * 128; i += 256)
        sW[i] = W[(i >> 7) * 256 + chunk * 128 + (i & 127)];
    __syncthreads();
    int warp = threadIdx.x >> 5, lane = threadIdx.x & 31;
    int rbase = (blockIdx.x * 8 + warp) * 4;
    if (rbase >= n) return;
    float h0[4], h1[4];
    #pragma unroll
    for (int i = 0; i < 4; i++) {
        int r = rbase + i;
        bool v = r < n;
        h0[i] = v ? g_h[r * FF + lane] : 0.f;
        h1[i] = v ? g_h[r * FF + lane + 32] : 0.f;
    }
    float4 acc[4];
    #pragma unroll
    for (int i = 0; i < 4; i++) acc[i] = make_float4(0.f, 0.f, 0.f, 0.f);
    #pragma unroll
    for (int kk = 0; kk < 32; kk++) {
        float4 wv = *(const float4*)&sW[kk * 128 + lane * 4];
        #pragma unroll
        for (int i = 0; i < 4; i++) {
            float hv = __shfl_sync(FULLM, h0[i], kk);
            acc[i].x = fmaf(hv, wv.x, acc[i].x); acc[i].y = fmaf(hv, wv.y, acc[i].y);
            acc[i].z = fmaf(hv, wv.z, acc[i].z); acc[i].w = fmaf(hv, wv.w, acc[i].w);
        }
    }
    #pragma unroll
    for (int kk = 0; kk < 32; kk++) {
        float4 wv = *(const float4*)&sW[(kk + 32) * 128 + lane * 4];
        #pragma unroll
        for (int i = 0; i < 4; i++) {
            float hv = __shfl_sync(FULLM, h1[i], kk);
            acc[i].x = fmaf(hv, wv.x, acc[i].x); acc[i].y = fmaf(hv, wv.y, acc[i].y);
            acc[i].z = fmaf(hv, wv.z, acc[i].z); acc[i].w = fmaf(hv, wv.w, acc[i].w);
        }
    }
    #pragma unroll
    for (int i = 0; i < 4; i++) {
        int r = rbase + i;
        if (r < n) *(float4*)&g_xh[r * 256 + chunk * 128 + lane * 4] = acc[i];
    }
}

// ---------------- attention coefficients + self-loop denominator seed ----------------
__global__ void k_attn(const float* __restrict__ att_s, const float* __restrict__ att_d, int n) {
    __shared__ float ss[256], sd[256];
    ss[threadIdx.x] = att_s[threadIdx.x];
    sd[threadIdx.x] = att_d[threadIdx.x];
    __syncthreads();
    int id = blockIdx.x * 256 + threadIdx.x;
    if (id >= n * HH) return;
    int nn = id >> 2, hh = id & 3;
    const float4* xr  = (const float4*)&g_xh[nn * 256 + hh * 64];
    const float4* as4 = (const float4*)&ss[hh * 64];
    const float4* ad4 = (const float4*)&sd[hh * 64];
    float sa = 0.f, sb = 0.f;
    #pragma unroll
    for (int i = 0; i < 16; i++) {
        float4 v = xr[i]; float4 a = as4[i]; float4 b = ad4[i];
        sa += v.x * a.x + v.y * a.y + v.z * a.z + v.w * a.w;
        sb += v.x * b.x + v.y * b.y + v.z * b.z + v.w * b.w;
    }
    g_asrc[id] = sa;
    g_adst[id] = sb;
    // self-loop term (exact: every dst has its loop; no max-shift needed, |e| is small)
    float el = lrelu(sa + sb, 0.2f);
    g_denom[id] = expf(el) + 1e-16f;
}

// ---------------- edge softmax: exp + denominator accumulation ----------------
__global__ void k_sumexp(const int* __restrict__ ei, int E) {
    int e = blockIdx.x * blockDim.x + threadIdx.x;
    if (e >= E) return;
    int s = ei[e], d = ei[E + e];
    float4 as = *(const float4*)&g_asrc[s * 4];
    float4 ad = *(const float4*)&g_adst[d * 4];
    float4 ex;
    ex.x = expf(lrelu(as.x + ad.x, 0.2f));
    ex.y = expf(lrelu(as.y + ad.y, 0.2f));
    ex.z = expf(lrelu(as.z + ad.z, 0.2f));
    ex.w = expf(lrelu(as.w + ad.w, 0.2f));
    *(float4*)&g_ex[e * 4] = ex;
    red4(&g_denom[d * 4], ex);
}

// ---------------- weighted aggregation: 16 threads per edge ----------------
__global__ void k_agg(const int* __restrict__ ei, int E, float* __restrict__ out) {
    int tid = blockIdx.x * blockDim.x + threadIdx.x;
    int e = tid >> 4;
    if (e >= E) return;
    int c = (tid & 15) << 2;
    int s = __ldg(&ei[e]);
    int d = __ldg(&ei[E + e]);
    float4 ex = *(const float4*)&g_ex[e * 4];
    float4 dn = *(const float4*)&g_denom[d * 4];
    float a0 = ex.x / dn.x, a1 = ex.y / dn.y, a2 = ex.z / dn.z, a3 = ex.w / dn.w;
    const float* xb = &g_xh[s * 256 + c];
    float4 v0 = *(const float4*)(xb);
    float4 v1 = *(const float4*)(xb + 64);
    float4 v2 = *(const float4*)(xb + 128);
    float4 v3 = *(const float4*)(xb + 192);
    float4 o;
    o.x = 0.25f * (a0 * v0.x + a1 * v1.x + a2 * v2.x + a3 * v3.x);
    o.y = 0.25f * (a0 * v0.y + a1 * v1.y + a2 * v2.y + a3 * v3.y);
    o.z = 0.25f * (a0 * v0.z + a1 * v1.z + a2 * v2.z + a3 * v3.z);
    o.w = 0.25f * (a0 * v0.w + a1 * v1.w + a2 * v2.w + a3 * v3.w);
    red4(out + d * FF + c, o);
}

// ---------------- finalize: self-loop contribution + bias + leaky ----------------
__global__ void k_final(const float* __restrict__ gatb, float* __restrict__ out, int n) {
    int tid = blockIdx.x * blockDim.x + threadIdx.x;
    int nn = tid >> 4;
    if (nn >= n) return;
    int c = (tid & 15) << 2;
    float4 as = *(const float4*)&g_asrc[nn * 4];
    float4 ad = *(const float4*)&g_adst[nn * 4];
    float4 dn = *(const float4*)&g_denom[nn * 4];
    float a0 = expf(lrelu(as.x + ad.x, 0.2f)) / dn.x;
    float a1 = expf(lrelu(as.y + ad.y, 0.2f)) / dn.y;
    float a2 = expf(lrelu(as.z + ad.z, 0.2f)) / dn.z;
    float a3 = expf(lrelu(as.w + ad.w, 0.2f)) / dn.w;
    const float* xb = &g_xh[nn * 256 + c];
    float4 v0 = *(const float4*)(xb);
    float4 v1 = *(const float4*)(xb + 64);
    float4 v2 = *(const float4*)(xb + 128);
    float4 v3 = *(const float4*)(xb + 192);
    float4 cur = *(const float4*)(out + nn * FF + c);
    float4 b = *(const float4*)(gatb + c);
    float4 r;
    r.x = lrelu(cur.x + 0.25f * (a0 * v0.x + a1 * v1.x + a2 * v2.x + a3 * v3.x) + b.x, 0.01f);
    r.y = lrelu(cur.y + 0.25f * (a0 * v0.y + a1 * v1.y + a2 * v2.y + a3 * v3.y) + b.y, 0.01f);
    r.z = lrelu(cur.z + 0.25f * (a0 * v0.z + a1 * v1.z + a2 * v2.z + a3 * v3.z) + b.z, 0.01f);
    r.w = lrelu(cur.w + 0.25f * (a0 * v0.w + a1 * v1.w + a2 * v2.w + a3 * v3.w) + b.w, 0.01f);
    *(float4*)(out + nn * FF + c) = r;
}

// ---------------- launch ----------------
extern "C" void kernel_launch(void* const* d_in, const int* in_sizes, int n_in,
                              void* d_out, int out_size) {
    const float* x      = (const float*)d_in[0];
    const int*   ei     = (const int*)d_in[1];
    const float* ea     = (const float*)d_in[2];
    const float* gamma  = (const float*)d_in[3];
    const float* beta   = (const float*)d_in[4];
    const float* chebw  = (const float*)d_in[5];
    const float* chebb  = (const float*)d_in[6];
    const float* gatw   = (const float*)d_in[7];
    const float* attsrc = (const float*)d_in[8];
    const float* attdst = (const float*)d_in[9];
    const float* gatb   = (const float*)d_in[10];
    float* out = (float*)d_out;

    int n = in_sizes[0] / FF;
    int E = in_sizes[1] / 2;

    k_zero_scratch<<<(NN * FF + 255) / 256, 256>>>(out, n * FF);
    k_ln<<<(n + 7) / 8, 256>>>(x, gamma, beta, n);
    k_deg<<<(E + 255) / 256, 256>>>(ei, ea, E);
    k_dinv<<<(n + 255) / 256, 256>>>(n);
    k_w<<<(E + 255) / 256, 256>>>(ei, ea, E);
    k_prop1<<<(E * 16 + 255) / 256, 256>>>(ei, E);
    k_prop2<<<(E * 16 + 255) / 256, 256>>>(ei, E);
    k_cheb<<<(n + 15) / 16, 256>>>(chebw, chebb, n);
    dim3 gg((n + 31) / 32, 2);
    k_gatgemm<<<gg, 256>>>(gatw, n);
    k_attn<<<(n * HH + 255) / 256, 256>>>(attsrc, attdst, n);
    k_sumexp<<<(E + 255) / 256, 256>>>(ei, E);
    k_agg<<<(E * 16 + 255) / 256, 256>>>(ei, E, out);
    k_final<<<(n * 16 + 255) / 256, 256>>>(gatb, out, n);
}

// round 16
// speedup vs baseline: 1.0604x; 1.0604x over previous
#include <cuda_runtime.h>
#include <cuda_bf16.h>

#define NN 50000
#define EE 800000
#define FF 64
#define HH 4
#define FULLM 0xffffffffu

// ---------------- scratch (device globals; no allocation allowed) ----------------
__device__ __align__(16) float g_xln[NN * FF];       // LayerNorm output = Tx0
__device__ __align__(16) float g_deg[NN];            // deg, then dinv in-place
__device__ __align__(16) float g_tx1[NN * FF];
__device__ __align__(16) float g_tx2[NN * FF];       // raw prop(Tx1); 2*.-Tx0 applied in GEMM
__device__ __align__(16) float g_h[NN * FF];         // Cheb output (leaky)
__device__ __align__(16) float g_xh[NN * HH * FF];   // GAT projected features
__device__ __align__(16) float g_asrc[NN * HH];
__device__ __align__(16) float g_adst[NN * HH];
// CSC structures (built per launch)
__device__ int   g_cnt[NN];       // in-degree histogram
__device__ int   g_rowptr[NN];    // exclusive scan of cnt
__device__ int   g_cur[NN];       // mutable fill cursor
__device__ int   g_csrc[EE];      // src node per dst-sorted edge
__device__ float g_cw[EE];        // laplacian weight per dst-sorted edge

__device__ __forceinline__ float lrelu(float x, float s) { return x >= 0.f ? x : s * x; }

// ---------------- zero degree + histogram ----------------
__global__ void k_zero(int n) {
    int i = blockIdx.x * blockDim.x + threadIdx.x;
    if (i < n) { g_deg[i] = 0.f; g_cnt[i] = 0; }
}

// ---------------- LayerNorm: warp per row ----------------
__global__ void k_ln(const float* __restrict__ x, const float* __restrict__ gamma,
                     const float* __restrict__ beta, int n) {
    int warp = threadIdx.x >> 5, lane = threadIdx.x & 31;
    int r = blockIdx.x * 8 + warp;
    if (r >= n) return;
    float2 v = *(const float2*)(x + r * FF + lane * 2);
    float s = v.x + v.y;
    #pragma unroll
    for (int o = 16; o; o >>= 1) s += __shfl_xor_sync(FULLM, s, o);
    float mu = s * (1.f / FF);
    float dx = v.x - mu, dy = v.y - mu;
    float sq = dx * dx + dy * dy;
    #pragma unroll
    for (int o = 16; o; o >>= 1) sq += __shfl_xor_sync(FULLM, sq, o);
    float inv = rsqrtf(sq * (1.f / FF) + 1e-5f);
    float2 gm = *(const float2*)(gamma + lane * 2);
    float2 bt = *(const float2*)(beta + lane * 2);
    float2 o2;
    o2.x = dx * inv * gm.x + bt.x;
    o2.y = dy * inv * gm.y + bt.y;
    *(float2*)(g_xln + r * FF + lane * 2) = o2;
}

// ---------------- degree (by src, weighted) + in-degree histogram (by dst) ----------------
__global__ void k_deghist(const int* __restrict__ ei, const float* __restrict__ ea, int E) {
    int e = blockIdx.x * blockDim.x + threadIdx.x;
    if (e >= E) return;
    atomicAdd(&g_deg[ei[e]], ea[e]);
    atomicAdd(&g_cnt[ei[E + e]], 1);
}
__global__ void k_dinv(int n) {
    int i = blockIdx.x * blockDim.x + threadIdx.x;
    if (i >= n) return;
    float d = g_deg[i];
    g_deg[i] = d > 0.f ? rsqrtf(d) : 0.f;
}

// ---------------- 1-block exclusive scan of g_cnt -> g_rowptr, g_cur ----------------
__global__ void k_scan(int n) {
    __shared__ int ssum[1024];
    int t = threadIdx.x;
    int per = (n + 1023) >> 10;
    int base = t * per;
    int sum = 0;
    for (int i = 0; i < per; i++) {
        int idx = base + i;
        if (idx < n) sum += g_cnt[idx];
    }
    ssum[t] = sum;
    __syncthreads();
    #pragma unroll
    for (int off = 1; off < 1024; off <<= 1) {
        int v = (t >= off) ? ssum[t - off] : 0;
        __syncthreads();
        ssum[t] += v;
        __syncthreads();
    }
    int run = (t == 0) ? 0 : ssum[t - 1];
    for (int i = 0; i < per; i++) {
        int idx = base + i;
        if (idx < n) {
            int c = g_cnt[idx];
            g_rowptr[idx] = run;
            g_cur[idx] = run;
            run += c;
        }
    }
}

// ---------------- CSC fill: permute src into dst-sorted order, weight computed inline ----------------
__global__ void k_fill(const int* __restrict__ ei, const float* __restrict__ ea, int E) {
    int e = blockIdx.x * blockDim.x + threadIdx.x;
    if (e >= E) return;
    int s = ei[e], d = ei[E + e];
    int pos = atomicAdd(&g_cur[d], 1);
    g_csrc[pos] = s;
    g_cw[pos] = -(__ldg(&g_deg[s]) * __ldg(&ea[e]) * __ldg(&g_deg[d]));
}

// ---------------- propagation: dst-centric gather, 16 threads per node ----------------
__device__ __forceinline__ void prop_body(const float* __restrict__ srcf,
                                          float* __restrict__ dstf, int n) {
    int tid = blockIdx.x * blockDim.x + threadIdx.x;
    int d = tid >> 4;
    if (d >= n) return;
    int c = (tid & 15) << 2;
    int beg = __ldg(&g_rowptr[d]);
    int cnt = __ldg(&g_cnt[d]);
    float4 acc = make_float4(0.f, 0.f, 0.f, 0.f);
    for (int j = beg; j < beg + cnt; j++) {
        int s = __ldg(&g_csrc[j]);
        float wv = __ldg(&g_cw[j]);
        float4 v = *(const float4*)(srcf + s * FF + c);
        acc.x = fmaf(wv, v.x, acc.x); acc.y = fmaf(wv, v.y, acc.y);
        acc.z = fmaf(wv, v.z, acc.z); acc.w = fmaf(wv, v.w, acc.w);
    }
    *(float4*)(dstf + d * FF + c) = acc;
}
__global__ void __launch_bounds__(256) k_prop1(int n) { prop_body(g_xln, g_tx1, n); }
__global__ void __launch_bounds__(256) k_prop2(int n) { prop_body(g_tx1, g_tx2, n); }

// ---------------- fused Cheb GEMM: [Tx0|Tx1|2*Tx2-Tx0] @ [192,64] + bias, leaky ----------------
__global__ void k_cheb(const float* __restrict__ W, const float* __restrict__ bias, int n) {
    __shared__ float sW[192 * 64];   // 48KB; cheb_w [3,64,64] is already this layout
    for (int i = threadIdx.x; i < 192 * 64; i += 256) sW[i] = W[i];
    __syncthreads();
    int warp = threadIdx.x >> 5, lane = threadIdx.x & 31;
    int r0 = (blockIdx.x * 8 + warp) * 2;
    int r1 = r0 + 1;
    if (r0 >= n) return;
    bool v1 = r1 < n;
    float a0r0 = g_xln[r0 * FF + lane], a1r0 = g_xln[r0 * FF + lane + 32];
    float b0r0 = g_tx1[r0 * FF + lane], b1r0 = g_tx1[r0 * FF + lane + 32];
    float c0r0 = 2.f * g_tx2[r0 * FF + lane] - a0r0;
    float c1r0 = 2.f * g_tx2[r0 * FF + lane + 32] - a1r0;
    float a0r1 = v1 ? g_xln[r1 * FF + lane] : 0.f, a1r1 = v1 ? g_xln[r1 * FF + lane + 32] : 0.f;
    float b0r1 = v1 ? g_tx1[r1 * FF + lane] : 0.f, b1r1 = v1 ? g_tx1[r1 * FF + lane + 32] : 0.f;
    float c0r1 = v1 ? 2.f * g_tx2[r1 * FF + lane] - a0r1 : 0.f;
    float c1r1 = v1 ? 2.f * g_tx2[r1 * FF + lane + 32] - a1r1 : 0.f;

    float acc00 = 0.f, acc01 = 0.f, acc10 = 0.f, acc11 = 0.f;
#define CHB(RA, RB, BASE)                                           \
    _Pragma("unroll")                                               \
    for (int kk = 0; kk < 32; kk++) {                               \
        float wa = sW[(BASE + kk) * 64 + lane];                     \
        float wb = sW[(BASE + kk) * 64 + lane + 32];                \
        float va = __shfl_sync(FULLM, RA, kk);                      \
        float vb = __shfl_sync(FULLM, RB, kk);                      \
        acc00 = fmaf(va, wa, acc00); acc01 = fmaf(va, wb, acc01);   \
        acc10 = fmaf(vb, wa, acc10); acc11 = fmaf(vb, wb, acc11);   \
    }
    CHB(a0r0, a0r1, 0)   CHB(a1r0, a1r1, 32)
    CHB(b0r0, b0r1, 64)  CHB(b1r0, b1r1, 96)
    CHB(c0r0, c0r1, 128) CHB(c1r0, c1r1, 160)
#undef CHB
    float bl = __ldg(&bias[lane]), bh = __ldg(&bias[lane + 32]);
    g_h[r0 * FF + lane]      = lrelu(acc00 + bl, 0.01f);
    g_h[r0 * FF + lane + 32] = lrelu(acc01 + bh, 0.01f);
    if (v1) {
        g_h[r1 * FF + lane]      = lrelu(acc10 + bl, 0.01f);
        g_h[r1 * FF + lane + 32] = lrelu(acc11 + bh, 0.01f);
    }
}

// ---------------- GAT projection + fused attention coefficients ----------------
// Each warp: 4 rows x 128 cols (chunk). Chunk holds heads {2*chunk, 2*chunk+1}.
__global__ void k_gatgemm(const float* __restrict__ W,
                          const float* __restrict__ att_s,
                          const float* __restrict__ att_d, int n) {
    __shared__ float sW[64 * 128];   // 32KB chunk of gat_w
    int chunk = blockIdx.y;
    for (int i = threadIdx.x; i < 64 * 128; i += 256)
        sW[i] = W[(i >> 7) * 256 + chunk * 128 + (i & 127)];
    __syncthreads();
    int warp = threadIdx.x >> 5, lane = threadIdx.x & 31;
    int rbase = (blockIdx.x * 8 + warp) * 4;
    if (rbase >= n) return;
    float h0[4], h1[4];
    #pragma unroll
    for (int i = 0; i < 4; i++) {
        int r = rbase + i;
        bool v = r < n;
        h0[i] = v ? g_h[r * FF + lane] : 0.f;
        h1[i] = v ? g_h[r * FF + lane + 32] : 0.f;
    }
    float4 acc[4];
    #pragma unroll
    for (int i = 0; i < 4; i++) acc[i] = make_float4(0.f, 0.f, 0.f, 0.f);
    #pragma unroll
    for (int kk = 0; kk < 32; kk++) {
        float4 wv = *(const float4*)&sW[kk * 128 + lane * 4];
        #pragma unroll
        for (int i = 0; i < 4; i++) {
            float hv = __shfl_sync(FULLM, h0[i], kk);
            acc[i].x = fmaf(hv, wv.x, acc[i].x); acc[i].y = fmaf(hv, wv.y, acc[i].y);
            acc[i].z = fmaf(hv, wv.z, acc[i].z); acc[i].w = fmaf(hv, wv.w, acc[i].w);
        }
    }
    #pragma unroll
    for (int kk = 0; kk < 32; kk++) {
        float4 wv = *(const float4*)&sW[(kk + 32) * 128 + lane * 4];
        #pragma unroll
        for (int i = 0; i < 4; i++) {
            float hv = __shfl_sync(FULLM, h1[i], kk);
            acc[i].x = fmaf(hv, wv.x, acc[i].x); acc[i].y = fmaf(hv, wv.y, acc[i].y);
            acc[i].z = fmaf(hv, wv.z, acc[i].z); acc[i].w = fmaf(hv, wv.w, acc[i].w);
        }
    }
    // attention partial dots: this lane covers cols chunk*128 + lane*4 .. +3
    float4 as4 = *(const float4*)(att_s + chunk * 128 + lane * 4);
    float4 ad4 = *(const float4*)(att_d + chunk * 128 + lane * 4);
    int head = chunk * 2 + (lane >> 4);   // head owned by this 16-lane group
    #pragma unroll
    for (int i = 0; i < 4; i++) {
        int r = rbase + i;
        if (r < n) *(float4*)&g_xh[r * 256 + chunk * 128 + lane * 4] = acc[i];
        float ps = acc[i].x * as4.x + acc[i].y * as4.y + acc[i].z * as4.z + acc[i].w * as4.w;
        float pd = acc[i].x * ad4.x + acc[i].y * ad4.y + acc[i].z * ad4.z + acc[i].w * ad4.w;
        #pragma unroll
        for (int o = 8; o; o >>= 1) {
            ps += __shfl_xor_sync(FULLM, ps, o);
            pd += __shfl_xor_sync(FULLM, pd, o);
        }
        if ((lane & 15) == 0 && r < n) {
            g_asrc[r * HH + head] = ps;
            g_adst[r * HH + head] = pd;
        }
    }
}

// ---------------- fused GAT softmax + aggregation: dst-centric, 16 threads/node ----------------
__global__ void __launch_bounds__(256) k_gatagg(const float* __restrict__ gatb,
                                                float* __restrict__ out, int n) {
    int tid = blockIdx.x * blockDim.x + threadIdx.x;
    int d = tid >> 4;
    if (d >= n) return;
    int c = (tid & 15) << 2;
    float4 ad = *(const float4*)&g_adst[d * HH];
    float4 asl = *(const float4*)&g_asrc[d * HH];
    // self-loop seed
    float e0 = __expf(lrelu(asl.x + ad.x, 0.2f));
    float e1 = __expf(lrelu(asl.y + ad.y, 0.2f));
    float e2 = __expf(lrelu(asl.z + ad.z, 0.2f));
    float e3 = __expf(lrelu(asl.w + ad.w, 0.2f));
    const float* xd = &g_xh[d * 256 + c];
    float4 v0 = *(const float4*)(xd);
    float4 v1 = *(const float4*)(xd + 64);
    float4 v2 = *(const float4*)(xd + 128);
    float4 v3 = *(const float4*)(xd + 192);
    float4 n0 = make_float4(e0 * v0.x, e0 * v0.y, e0 * v0.z, e0 * v0.w);
    float4 n1 = make_float4(e1 * v1.x, e1 * v1.y, e1 * v1.z, e1 * v1.w);
    float4 n2 = make_float4(e2 * v2.x, e2 * v2.y, e2 * v2.z, e2 * v2.w);
    float4 n3 = make_float4(e3 * v3.x, e3 * v3.y, e3 * v3.z, e3 * v3.w);
    float den0 = e0, den1 = e1, den2 = e2, den3 = e3;
    int beg = __ldg(&g_rowptr[d]);
    int cnt = __ldg(&g_cnt[d]);
    for (int j = beg; j < beg + cnt; j++) {
        int s = __ldg(&g_csrc[j]);
        float4 as = *(const float4*)&g_asrc[s * HH];
        float x0 = __expf(lrelu(as.x + ad.x, 0.2f));
        float x1 = __expf(lrelu(as.y + ad.y, 0.2f));
        float x2 = __expf(lrelu(as.z + ad.z, 0.2f));
        float x3 = __expf(lrelu(as.w + ad.w, 0.2f));
        const float* xs = &g_xh[s * 256 + c];
        float4 s0 = *(const float4*)(xs);
        float4 s1 = *(const float4*)(xs + 64);
        float4 s2 = *(const float4*)(xs + 128);
        float4 s3 = *(const float4*)(xs + 192);
        n0.x = fmaf(x0, s0.x, n0.x); n0.y = fmaf(x0, s0.y, n0.y);
        n0.z = fmaf(x0, s0.z, n0.z); n0.w = fmaf(x0, s0.w, n0.w);
        n1.x = fmaf(x1, s1.x, n1.x); n1.y = fmaf(x1, s1.y, n1.y);
        n1.z = fmaf(x1, s1.z, n1.z); n1.w = fmaf(x1, s1.w, n1.w);
        n2.x = fmaf(x2, s2.x, n2.x); n2.y = fmaf(x2, s2.y, n2.y);
        n2.z = fmaf(x2, s2.z, n2.z); n2.w = fmaf(x2, s2.w, n2.w);
        n3.x = fmaf(x3, s3.x, n3.x); n3.y = fmaf(x3, s3.y, n3.y);
        n3.z = fmaf(x3, s3.z, n3.z); n3.w = fmaf(x3, s3.w, n3.w);
        den0 += x0; den1 += x1; den2 += x2; den3 += x3;
    }
    float r0 = 0.25f / (den0 + 1e-16f);
    float r1 = 0.25f / (den1 + 1e-16f);
    float r2 = 0.25f / (den2 + 1e-16f);
    float r3 = 0.25f / (den3 + 1e-16f);
    float4 b = *(const float4*)(gatb + c);
    float4 o;
    o.x = lrelu(n0.x * r0 + n1.x * r1 + n2.x * r2 + n3.x * r3 + b.x, 0.01f);
    o.y = lrelu(n0.y * r0 + n1.y * r1 + n2.y * r2 + n3.y * r3 + b.y, 0.01f);
    o.z = lrelu(n0.z * r0 + n1.z * r1 + n2.z * r2 + n3.z * r3 + b.z, 0.01f);
    o.w = lrelu(n0.w * r0 + n1.w * r1 + n2.w * r2 + n3.w * r3 + b.w, 0.01f);
    *(float4*)(out + d * FF + c) = o;
}

// ---------------- launch ----------------
extern "C" void kernel_launch(void* const* d_in, const int* in_sizes, int n_in,
                              void* d_out, int out_size) {
    const float* x      = (const float*)d_in[0];
    const int*   ei     = (const int*)d_in[1];
    const float* ea     = (const float*)d_in[2];
    const float* gamma  = (const float*)d_in[3];
    const float* beta   = (const float*)d_in[4];
    const float* chebw  = (const float*)d_in[5];
    const float* chebb  = (const float*)d_in[6];
    const float* gatw   = (const float*)d_in[7];
    const float* attsrc = (const float*)d_in[8];
    const float* attdst = (const float*)d_in[9];
    const float* gatb   = (const float*)d_in[10];
    float* out = (float*)d_out;

    int n = in_sizes[0] / FF;
    int E = in_sizes[1] / 2;

    k_zero<<<(n + 255) / 256, 256>>>(n);
    k_ln<<<(n + 7) / 8, 256>>>(x, gamma, beta, n);
    k_deghist<<<(E + 255) / 256, 256>>>(ei, ea, E);
    k_dinv<<<(n + 255) / 256, 256>>>(n);
    k_scan<<<1, 1024>>>(n);
    k_fill<<<(E + 255) / 256, 256>>>(ei, ea, E);
    k_prop1<<<(n * 16 + 255) / 256, 256>>>(n);
    k_prop2<<<(n * 16 + 255) / 256, 256>>>(n);
    k_cheb<<<(n + 15) / 16, 256>>>(chebw, chebb, n);
    dim3 gg((n + 31) / 32, 2);
    k_gatgemm<<<gg, 256>>>(gatw, attsrc, attdst, n);
    k_gatagg<<<(n * 16 + 255) / 256, 256>>>(gatb, out, n);
}